// round 2
// baseline (speedup 1.0000x reference)
#include <cuda_runtime.h>
#include <math.h>

#define NN 50000
#define EE 400000
#define HC 128
#define EDIM 16
#define BN_EPS 1e-5f

// ---------------- scratch (device globals; no allocation allowed) ----------------
__device__ float g_Q[(size_t)NN * HC];
__device__ float g_K[(size_t)NN * HC];
__device__ float g_V[(size_t)NN * HC];
__device__ float g_S[(size_t)NN * HC];   // skip; later overwritten with y = attn + skip

__device__ int g_deg[NN];
__device__ int g_cur[NN];
__device__ int g_off[NN + 1];
__device__ int g_eids[EE];
__device__ int g_bsum[256];
__device__ int g_boff[256];
__device__ float g_bnsum[HC];
__device__ float g_bnsq[HC];

// ---------------- CSR build ----------------
__global__ void k_zero_csr() {
    int i = blockIdx.x * blockDim.x + threadIdx.x;
    if (i < NN) { g_deg[i] = 0; g_cur[i] = 0; }
}

__global__ void k_hist(const int* __restrict__ dst) {
    int e = blockIdx.x * blockDim.x + threadIdx.x;
    if (e < EE) atomicAdd(&g_deg[dst[e]], 1);
}

__global__ void k_scan1() {
    __shared__ int sh[256];
    int tid = threadIdx.x;
    int i = blockIdx.x * 256 + tid;
    int v = (i < NN) ? g_deg[i] : 0;
    sh[tid] = v;
    __syncthreads();
    for (int o = 1; o < 256; o <<= 1) {
        int t = (tid >= o) ? sh[tid - o] : 0;
        __syncthreads();
        sh[tid] += t;
        __syncthreads();
    }
    if (i < NN) g_off[i] = sh[tid] - v;           // exclusive
    if (tid == 255) g_bsum[blockIdx.x] = sh[255]; // block total
}

__global__ void k_scan2(int nb) {
    __shared__ int sh[256];
    int tid = threadIdx.x;
    int v = (tid < nb) ? g_bsum[tid] : 0;
    sh[tid] = v;
    __syncthreads();
    for (int o = 1; o < 256; o <<= 1) {
        int t = (tid >= o) ? sh[tid - o] : 0;
        __syncthreads();
        sh[tid] += t;
        __syncthreads();
    }
    g_boff[tid] = sh[tid] - v;
}

__global__ void k_scan3() {
    int i = blockIdx.x * 256 + threadIdx.x;
    if (i < NN) g_off[i] += g_boff[blockIdx.x];
    if (i == 0) g_off[NN] = EE;
}

__global__ void k_fill(const int* __restrict__ dst) {
    int e = blockIdx.x * blockDim.x + threadIdx.x;
    if (e < EE) {
        int d = dst[e];
        int pos = g_off[d] + atomicAdd(&g_cur[d], 1);
        g_eids[pos] = e;
    }
}

// ---------------- fp32 SGEMM: C[M,128] = A[M,128] @ W[128,128] + bias ----------------
// BM=128, BN=128, BK=8, 256 threads, 8x8 per thread
__global__ void __launch_bounds__(256, 2) k_sgemm(
    const float* __restrict__ A, const float* __restrict__ W,
    const float* __restrict__ bias, float* __restrict__ C, int M)
{
    __shared__ __align__(16) float As[8][128];
    __shared__ __align__(16) float Bs[8][128];
    int tid = threadIdx.x;
    int brow = blockIdx.x * 128;
    int tr = (tid >> 4) * 8;
    int tc = (tid & 15) * 8;
    float acc[8][8];
#pragma unroll
    for (int i = 0; i < 8; i++)
#pragma unroll
        for (int j = 0; j < 8; j++) acc[i][j] = 0.f;

    int aRow = tid >> 1;          // 0..127
    int aCol = (tid & 1) * 4;     // 0 or 4
    int bRow = tid >> 5;          // 0..7
    int bCol = (tid & 31) * 4;    // 0..124

    for (int k0 = 0; k0 < 128; k0 += 8) {
        int gr = brow + aRow;
        float4 av = make_float4(0.f, 0.f, 0.f, 0.f);
        if (gr < M) av = *(const float4*)&A[(size_t)gr * 128 + k0 + aCol];
        As[aCol + 0][aRow] = av.x;
        As[aCol + 1][aRow] = av.y;
        As[aCol + 2][aRow] = av.z;
        As[aCol + 3][aRow] = av.w;
        *(float4*)&Bs[bRow][bCol] = *(const float4*)&W[(size_t)(k0 + bRow) * 128 + bCol];
        __syncthreads();
#pragma unroll
        for (int k = 0; k < 8; k++) {
            float a[8], b[8];
            *(float4*)&a[0] = *(float4*)&As[k][tr];
            *(float4*)&a[4] = *(float4*)&As[k][tr + 4];
            *(float4*)&b[0] = *(float4*)&Bs[k][tc];
            *(float4*)&b[4] = *(float4*)&Bs[k][tc + 4];
#pragma unroll
            for (int i = 0; i < 8; i++)
#pragma unroll
                for (int j = 0; j < 8; j++) acc[i][j] += a[i] * b[j];
        }
        __syncthreads();
    }

    float bb[8];
    *(float4*)&bb[0] = *(const float4*)&bias[tc];
    *(float4*)&bb[4] = *(const float4*)&bias[tc + 4];
#pragma unroll
    for (int i = 0; i < 8; i++) {
        int gr = brow + tr + i;
        if (gr < M) {
            float4 o0 = make_float4(acc[i][0] + bb[0], acc[i][1] + bb[1],
                                    acc[i][2] + bb[2], acc[i][3] + bb[3]);
            float4 o1 = make_float4(acc[i][4] + bb[4], acc[i][5] + bb[5],
                                    acc[i][6] + bb[6], acc[i][7] + bb[7]);
            *(float4*)&C[(size_t)gr * 128 + tc]     = o0;
            *(float4*)&C[(size_t)gr * 128 + tc + 4] = o1;
        }
    }
}

// ---------------- edge attention: one warp per dst node, online softmax ----------------
// lane l owns channels [4l, 4l+4); head h = l/8; per-head reduce via 8-lane bfly.
__global__ void __launch_bounds__(256) k_edge(
    const float* __restrict__ EA,   // [E,16]
    const float* __restrict__ EW,   // [16,128]
    const int* __restrict__ src)
{
    __shared__ __align__(16) float4 ews[16 * 32];   // 16 rows x 128 cols as float4
    for (int i = threadIdx.x; i < 16 * 32; i += 256)
        ews[i] = ((const float4*)EW)[i];
    __syncthreads();

    int warp = (blockIdx.x * 256 + threadIdx.x) >> 5;
    int lane = threadIdx.x & 31;
    if (warp >= NN) return;
    int node = warp;
    int beg = g_off[node], end = g_off[node + 1];

    float4 qv = *(const float4*)&g_Q[(size_t)node * HC + lane * 4];

    float m = -1e30f;
    float s = 0.f;
    float ax = 0.f, ay = 0.f, az = 0.f, aw = 0.f;

    for (int p = beg; p < end; p++) {
        int e = g_eids[p];
        int sn = src[e];
        float eav = (lane < EDIM) ? EA[(size_t)e * EDIM + lane] : 0.f;

        float ex = 0.f, ey = 0.f, ez = 0.f, ew_ = 0.f;
#pragma unroll
        for (int d = 0; d < EDIM; d++) {
            float w = __shfl_sync(0xffffffffu, eav, d);
            float4 wc = ews[d * 32 + lane];
            ex += w * wc.x; ey += w * wc.y; ez += w * wc.z; ew_ += w * wc.w;
        }

        float4 kv = *(const float4*)&g_K[(size_t)sn * HC + lane * 4];
        float4 vv = *(const float4*)&g_V[(size_t)sn * HC + lane * 4];

        float part = qv.x * (kv.x + ex) + qv.y * (kv.y + ey)
                   + qv.z * (kv.z + ez) + qv.w * (kv.w + ew_);
        part += __shfl_xor_sync(0xffffffffu, part, 1);
        part += __shfl_xor_sync(0xffffffffu, part, 2);
        part += __shfl_xor_sync(0xffffffffu, part, 4);
        float a = part * 0.17677669529663687f;   // 1/sqrt(32)

        float nm = fmaxf(m, a);
        float sc = __expf(m - nm);
        float pe = __expf(a - nm);
        s = s * sc + pe;
        ax = ax * sc + pe * (vv.x + ex);
        ay = ay * sc + pe * (vv.y + ey);
        az = az * sc + pe * (vv.z + ez);
        aw = aw * sc + pe * (vv.w + ew_);
        m = nm;
    }

    float inv = (end > beg) ? (1.f / s) : 0.f;
    size_t o = (size_t)node * HC + lane * 4;
    float4 sv = *(const float4*)&g_S[o];
    float4 y = make_float4(ax * inv + sv.x, ay * inv + sv.y,
                           az * inv + sv.z, aw * inv + sv.w);
    *(float4*)&g_S[o] = y;   // y = attn_out + skip  (in place)
}

// ---------------- batchnorm + relu ----------------
__global__ void k_zero_bn() {
    int t = threadIdx.x;
    if (t < HC) { g_bnsum[t] = 0.f; g_bnsq[t] = 0.f; }
}

__global__ void k_bn_reduce() {
    int c = threadIdx.x;   // 128 threads
    float sum = 0.f, sq = 0.f;
    for (int n = blockIdx.x; n < NN; n += gridDim.x) {
        float v = g_S[(size_t)n * HC + c];
        sum += v; sq += v * v;
    }
    atomicAdd(&g_bnsum[c], sum);
    atomicAdd(&g_bnsq[c], sq);
}

__global__ void k_bn_apply(const float* __restrict__ gamma,
                           const float* __restrict__ beta,
                           float* __restrict__ out)
{
    int i = blockIdx.x * blockDim.x + threadIdx.x;
    if (i >= NN * HC) return;
    int c = i & 127;
    float mean = g_bnsum[c] * (1.f / NN);
    float var = fmaf(-mean, mean, g_bnsq[c] * (1.f / NN));
    float v = (g_S[i] - mean) * rsqrtf(var + BN_EPS) * gamma[c] + beta[c];
    out[i] = fmaxf(v, 0.f);
}

// ---------------- driver ----------------
extern "C" void kernel_launch(void* const* d_in, const int* in_sizes, int n_in,
                              void* d_out, int out_size)
{
    const float* x  = (const float*)d_in[0];
    const int*   ei = (const int*)d_in[1];
    const float* ea = (const float*)d_in[2];
    const int* src = ei;
    const int* dst = ei + EE;

    float* out = (float*)d_out;
    float* x1 = out;
    float* x2 = out + (size_t)NN * HC;

    float *Q, *K, *V, *S;
    cudaGetSymbolAddress((void**)&Q, g_Q);
    cudaGetSymbolAddress((void**)&K, g_K);
    cudaGetSymbolAddress((void**)&V, g_V);
    cudaGetSymbolAddress((void**)&S, g_S);

    const int NB1 = (NN + 255) / 256;   // 196

    // CSR build (shared by both layers)
    k_zero_csr<<<NB1, 256>>>();
    k_hist<<<(EE + 255) / 256, 256>>>(dst);
    k_scan1<<<NB1, 256>>>();
    k_scan2<<<1, 256>>>(NB1);
    k_scan3<<<NB1, 256>>>();
    k_fill<<<(EE + 255) / 256, 256>>>(dst);

    const float* in_ptr = x;
    for (int L = 0; L < 2; L++) {
        int b = 3 + L * 11;
        const float* qw = (const float*)d_in[b + 0];
        const float* qb = (const float*)d_in[b + 1];
        const float* kw = (const float*)d_in[b + 2];
        const float* kb = (const float*)d_in[b + 3];
        const float* vw = (const float*)d_in[b + 4];
        const float* vb = (const float*)d_in[b + 5];
        const float* ew = (const float*)d_in[b + 6];
        const float* sw = (const float*)d_in[b + 7];
        const float* sb = (const float*)d_in[b + 8];
        const float* bg = (const float*)d_in[b + 9];
        const float* bb = (const float*)d_in[b + 10];

        dim3 gg((NN + 127) / 128);
        k_sgemm<<<gg, 256>>>(in_ptr, qw, qb, Q, NN);
        k_sgemm<<<gg, 256>>>(in_ptr, kw, kb, K, NN);
        k_sgemm<<<gg, 256>>>(in_ptr, vw, vb, V, NN);
        k_sgemm<<<gg, 256>>>(in_ptr, sw, sb, S, NN);

        k_edge<<<(NN * 32 + 255) / 256, 256>>>(ea, ew, src);

        k_zero_bn<<<1, 128>>>();
        k_bn_reduce<<<512, 128>>>();
        k_bn_apply<<<(NN * HC + 255) / 256, 256>>>(bg, bb, (L == 0) ? x1 : x2);

        in_ptr = x1;
    }
}

// round 3
// speedup vs baseline: 1.2096x; 1.2096x over previous
#include <cuda_runtime.h>
#include <math.h>

#define NN 50000
#define EE 400000
#define HC 128
#define EDIM 16
#define BN_EPS 1e-5f

// ---------------- scratch (device globals; no allocation allowed) ----------------
__device__ float g_Q[(size_t)NN * HC];
__device__ float g_K[(size_t)NN * HC];
__device__ float g_V[(size_t)NN * HC];
__device__ float g_S[(size_t)NN * HC];   // skip; later overwritten with y = attn + skip

__device__ int g_deg[NN];
__device__ int g_cur[NN];
__device__ int g_off[NN + 1];
__device__ int g_eids[EE];
__device__ int g_bsum[256];
__device__ int g_boff[256];
__device__ float g_bnsum[HC];
__device__ float g_bnsq[HC];

// ---------------- CSR build ----------------
__global__ void k_zero_csr() {
    int i = blockIdx.x * blockDim.x + threadIdx.x;
    if (i < NN) { g_deg[i] = 0; g_cur[i] = 0; }
}

__global__ void k_hist(const int* __restrict__ dst) {
    int e = blockIdx.x * blockDim.x + threadIdx.x;
    if (e < EE) atomicAdd(&g_deg[dst[e]], 1);
}

__global__ void k_scan1() {
    __shared__ int sh[256];
    int tid = threadIdx.x;
    int i = blockIdx.x * 256 + tid;
    int v = (i < NN) ? g_deg[i] : 0;
    sh[tid] = v;
    __syncthreads();
    for (int o = 1; o < 256; o <<= 1) {
        int t = (tid >= o) ? sh[tid - o] : 0;
        __syncthreads();
        sh[tid] += t;
        __syncthreads();
    }
    if (i < NN) g_off[i] = sh[tid] - v;           // exclusive
    if (tid == 255) g_bsum[blockIdx.x] = sh[255]; // block total
}

__global__ void k_scan2(int nb) {
    __shared__ int sh[256];
    int tid = threadIdx.x;
    int v = (tid < nb) ? g_bsum[tid] : 0;
    sh[tid] = v;
    __syncthreads();
    for (int o = 1; o < 256; o <<= 1) {
        int t = (tid >= o) ? sh[tid - o] : 0;
        __syncthreads();
        sh[tid] += t;
        __syncthreads();
    }
    g_boff[tid] = sh[tid] - v;
}

__global__ void k_scan3() {
    int i = blockIdx.x * 256 + threadIdx.x;
    if (i < NN) g_off[i] += g_boff[blockIdx.x];
    if (i == 0) g_off[NN] = EE;
}

__global__ void k_fill(const int* __restrict__ dst) {
    int e = blockIdx.x * blockDim.x + threadIdx.x;
    if (e < EE) {
        int d = dst[e];
        int pos = g_off[d] + atomicAdd(&g_cur[d], 1);
        g_eids[pos] = e;
    }
}

// ---------------- 3xTF32 tensor-core GEMM: C[M,128] = A[M,128] @ W[128,128] + bias ----
// BM=128, BN=128, BK=64 (2 chunks), 256 threads (8 warps, 2x4 layout, 64x32 warp tile)
// smem: hi/lo interleaved per element so each fragment scalar is one LDS.64.
#define SA 136   // A row stride in floats (128 interleaved + 8 pad)
#define SB 264   // B row stride in floats (256 interleaved + 8 pad)
#define GEMM_SMEM ((128 * SA + 64 * SB) * 4)

__device__ __forceinline__ void tf32_split(float a, float& h, float& l) {
    unsigned hb, lb;
    asm("cvt.rna.tf32.f32 %0, %1;" : "=r"(hb) : "f"(a));
    float hf = __uint_as_float(hb);
    float r = a - hf;
    asm("cvt.rna.tf32.f32 %0, %1;" : "=r"(lb) : "f"(r));
    h = hf;
    l = __uint_as_float(lb);
}

__device__ __forceinline__ void mma8(float* d, unsigned a0, unsigned a1, unsigned a2,
                                     unsigned a3, unsigned b0, unsigned b1) {
    asm volatile(
        "mma.sync.aligned.m16n8k8.row.col.f32.tf32.tf32.f32 "
        "{%0,%1,%2,%3}, {%4,%5,%6,%7}, {%8,%9}, {%0,%1,%2,%3};\n"
        : "+f"(d[0]), "+f"(d[1]), "+f"(d[2]), "+f"(d[3])
        : "r"(a0), "r"(a1), "r"(a2), "r"(a3), "r"(b0), "r"(b1));
}

__global__ void __launch_bounds__(256, 1) k_mma_gemm(
    const float* __restrict__ A, const float* __restrict__ W,
    const float* __restrict__ bias, float* __restrict__ C, int M)
{
    extern __shared__ float sm[];
    float* As = sm;              // [128][SA]  hi/lo interleaved over k
    float* Bs = sm + 128 * SA;   // [64][SB]   hi/lo interleaved over n

    int tid = threadIdx.x;
    int wid = tid >> 5, lane = tid & 31;
    int g = lane >> 2, tig = lane & 3;
    int m0 = (wid & 1) * 64;
    int n0 = (wid >> 1) * 32;
    int brow = blockIdx.x * 128;

    float acc[4][4][4];
#pragma unroll
    for (int i = 0; i < 4; i++)
#pragma unroll
        for (int j = 0; j < 4; j++)
#pragma unroll
            for (int r = 0; r < 4; r++) acc[i][j][r] = 0.f;

    for (int k0 = 0; k0 < 128; k0 += 64) {
        // load A chunk [128 x 64]: each thread: 16 x (float2 gmem -> float4 smem)
#pragma unroll
        for (int j = 0; j < 16; j++) {
            int idx = tid + j * 256;           // 0..4095
            int row = idx >> 5;                // 32 float2 per row
            int c2 = idx & 31;
            int grow = brow + row;
            float2 v = make_float2(0.f, 0.f);
            if (grow < M) v = *(const float2*)&A[(size_t)grow * 128 + k0 + c2 * 2];
            float hx, lx, hy, ly;
            tf32_split(v.x, hx, lx);
            tf32_split(v.y, hy, ly);
            *(float4*)&As[row * SA + c2 * 4] = make_float4(hx, lx, hy, ly);
        }
        // load W chunk [64 x 128]
#pragma unroll
        for (int j = 0; j < 16; j++) {
            int idx = tid + j * 256;
            int kr = idx >> 6;                 // 64 float2 per row
            int c2 = idx & 63;
            float2 v = *(const float2*)&W[(size_t)(k0 + kr) * 128 + c2 * 2];
            float hx, lx, hy, ly;
            tf32_split(v.x, hx, lx);
            tf32_split(v.y, hy, ly);
            *(float4*)&Bs[kr * SB + c2 * 4] = make_float4(hx, lx, hy, ly);
        }
        __syncthreads();

#pragma unroll
        for (int ks = 0; ks < 8; ks++) {
            int kk = ks * 8;
            unsigned ah[4][4], al[4][4], bh[4][2], bl[4][2];
#pragma unroll
            for (int mf = 0; mf < 4; mf++) {
                const float* ab = &As[(m0 + mf * 16 + g) * SA + 2 * (kk + tig)];
                float2 v0 = *(const float2*)ab;             // a0: (g,   k)
                float2 v2 = *(const float2*)(ab + 8);       // a2: (g,   k+4)
                float2 v1 = *(const float2*)(ab + 8 * SA);  // a1: (g+8, k)
                float2 v3 = *(const float2*)(ab + 8 * SA + 8);
                ah[mf][0] = __float_as_uint(v0.x); al[mf][0] = __float_as_uint(v0.y);
                ah[mf][1] = __float_as_uint(v1.x); al[mf][1] = __float_as_uint(v1.y);
                ah[mf][2] = __float_as_uint(v2.x); al[mf][2] = __float_as_uint(v2.y);
                ah[mf][3] = __float_as_uint(v3.x); al[mf][3] = __float_as_uint(v3.y);
            }
#pragma unroll
            for (int nf = 0; nf < 4; nf++) {
                const float* bp = &Bs[(kk + tig) * SB + 2 * (n0 + nf * 8 + g)];
                float2 w0 = *(const float2*)bp;             // b0: (k,   n)
                float2 w1 = *(const float2*)(bp + 4 * SB);  // b1: (k+4, n)
                bh[nf][0] = __float_as_uint(w0.x); bl[nf][0] = __float_as_uint(w0.y);
                bh[nf][1] = __float_as_uint(w1.x); bl[nf][1] = __float_as_uint(w1.y);
            }
#pragma unroll
            for (int mf = 0; mf < 4; mf++)
#pragma unroll
                for (int nf = 0; nf < 4; nf++) {
                    float* d = acc[mf][nf];
                    mma8(d, ah[mf][0], ah[mf][1], ah[mf][2], ah[mf][3], bh[nf][0], bh[nf][1]);
                    mma8(d, ah[mf][0], ah[mf][1], ah[mf][2], ah[mf][3], bl[nf][0], bl[nf][1]);
                    mma8(d, al[mf][0], al[mf][1], al[mf][2], al[mf][3], bh[nf][0], bh[nf][1]);
                }
        }
        __syncthreads();
    }

    // epilogue: add bias, store
#pragma unroll
    for (int nf = 0; nf < 4; nf++) {
        int col = n0 + nf * 8 + tig * 2;
        float b0v = bias[col], b1v = bias[col + 1];
#pragma unroll
        for (int mf = 0; mf < 4; mf++) {
            int r0 = brow + m0 + mf * 16 + g;
            float* d = acc[mf][nf];
            if (r0 < M)
                *(float2*)&C[(size_t)r0 * 128 + col] = make_float2(d[0] + b0v, d[1] + b1v);
            if (r0 + 8 < M)
                *(float2*)&C[(size_t)(r0 + 8) * 128 + col] = make_float2(d[2] + b0v, d[3] + b1v);
        }
    }
}

// ---------------- edge attention: one warp per dst node, online softmax ----------------
__global__ void __launch_bounds__(256) k_edge(
    const float* __restrict__ EA,   // [E,16]
    const float* __restrict__ EW,   // [16,128]
    const int* __restrict__ src)
{
    __shared__ __align__(16) float4 ews[16 * 32];   // 16 rows x 128 cols as float4
    for (int i = threadIdx.x; i < 16 * 32; i += 256)
        ews[i] = ((const float4*)EW)[i];
    __syncthreads();

    int warp = (blockIdx.x * 256 + threadIdx.x) >> 5;
    int lane = threadIdx.x & 31;
    if (warp >= NN) return;
    int node = warp;
    int beg = g_off[node], end = g_off[node + 1];

    float4 qv = *(const float4*)&g_Q[(size_t)node * HC + lane * 4];

    float m = -1e30f;
    float s = 0.f;
    float ax = 0.f, ay = 0.f, az = 0.f, aw = 0.f;

    for (int p = beg; p < end; p++) {
        int e = g_eids[p];
        int sn = src[e];
        float eav = (lane < EDIM) ? EA[(size_t)e * EDIM + lane] : 0.f;

        float ex = 0.f, ey = 0.f, ez = 0.f, ew_ = 0.f;
#pragma unroll
        for (int d = 0; d < EDIM; d++) {
            float w = __shfl_sync(0xffffffffu, eav, d);
            float4 wc = ews[d * 32 + lane];
            ex += w * wc.x; ey += w * wc.y; ez += w * wc.z; ew_ += w * wc.w;
        }

        float4 kv = *(const float4*)&g_K[(size_t)sn * HC + lane * 4];
        float4 vv = *(const float4*)&g_V[(size_t)sn * HC + lane * 4];

        float part = qv.x * (kv.x + ex) + qv.y * (kv.y + ey)
                   + qv.z * (kv.z + ez) + qv.w * (kv.w + ew_);
        part += __shfl_xor_sync(0xffffffffu, part, 1);
        part += __shfl_xor_sync(0xffffffffu, part, 2);
        part += __shfl_xor_sync(0xffffffffu, part, 4);
        float a = part * 0.17677669529663687f;   // 1/sqrt(32)

        float nm = fmaxf(m, a);
        float sc = __expf(m - nm);
        float pe = __expf(a - nm);
        s = s * sc + pe;
        ax = ax * sc + pe * (vv.x + ex);
        ay = ay * sc + pe * (vv.y + ey);
        az = az * sc + pe * (vv.z + ez);
        aw = aw * sc + pe * (vv.w + ew_);
        m = nm;
    }

    float inv = (end > beg) ? (1.f / s) : 0.f;
    size_t o = (size_t)node * HC + lane * 4;
    float4 sv = *(const float4*)&g_S[o];
    float4 y = make_float4(ax * inv + sv.x, ay * inv + sv.y,
                           az * inv + sv.z, aw * inv + sv.w);
    *(float4*)&g_S[o] = y;   // y = attn_out + skip  (in place)
}

// ---------------- batchnorm + relu ----------------
__global__ void k_zero_bn() {
    int t = threadIdx.x;
    if (t < HC) { g_bnsum[t] = 0.f; g_bnsq[t] = 0.f; }
}

__global__ void k_bn_reduce() {
    int c = threadIdx.x;   // 128 threads
    float sum = 0.f, sq = 0.f;
    for (int n = blockIdx.x; n < NN; n += gridDim.x) {
        float v = g_S[(size_t)n * HC + c];
        sum += v; sq += v * v;
    }
    atomicAdd(&g_bnsum[c], sum);
    atomicAdd(&g_bnsq[c], sq);
}

__global__ void k_bn_apply(const float* __restrict__ gamma,
                           const float* __restrict__ beta,
                           float* __restrict__ out)
{
    int i = blockIdx.x * blockDim.x + threadIdx.x;
    if (i >= NN * HC) return;
    int c = i & 127;
    float mean = g_bnsum[c] * (1.f / NN);
    float var = fmaf(-mean, mean, g_bnsq[c] * (1.f / NN));
    float v = (g_S[i] - mean) * rsqrtf(var + BN_EPS) * gamma[c] + beta[c];
    out[i] = fmaxf(v, 0.f);
}

// ---------------- driver ----------------
extern "C" void kernel_launch(void* const* d_in, const int* in_sizes, int n_in,
                              void* d_out, int out_size)
{
    const float* x  = (const float*)d_in[0];
    const int*   ei = (const int*)d_in[1];
    const float* ea = (const float*)d_in[2];
    const int* src = ei;
    const int* dst = ei + EE;

    float* out = (float*)d_out;
    float* x1 = out;
    float* x2 = out + (size_t)NN * HC;

    float *Q, *K, *V, *S;
    cudaGetSymbolAddress((void**)&Q, g_Q);
    cudaGetSymbolAddress((void**)&K, g_K);
    cudaGetSymbolAddress((void**)&V, g_V);
    cudaGetSymbolAddress((void**)&S, g_S);

    static int smem_set = 0;
    if (!smem_set) {
        cudaFuncSetAttribute(k_mma_gemm, cudaFuncAttributeMaxDynamicSharedMemorySize,
                             GEMM_SMEM);
        smem_set = 1;
    }

    const int NB1 = (NN + 255) / 256;   // 196
    const dim3 gg((NN + 127) / 128);    // 391

    const float* in_ptr = x;
    for (int L = 0; L < 2; L++) {
        int b = 3 + L * 11;
        const float* qw = (const float*)d_in[b + 0];
        const float* qb = (const float*)d_in[b + 1];
        const float* kw = (const float*)d_in[b + 2];
        const float* kb = (const float*)d_in[b + 3];
        const float* vw = (const float*)d_in[b + 4];
        const float* vb = (const float*)d_in[b + 5];
        const float* ew = (const float*)d_in[b + 6];
        const float* sw = (const float*)d_in[b + 7];
        const float* sb = (const float*)d_in[b + 8];
        const float* bg = (const float*)d_in[b + 9];
        const float* bb = (const float*)d_in[b + 10];

        if (L == 0) {
            // interleave CSR build with GEMMs so ncu -s 5 -c 1 lands on a GEMM
            k_zero_csr<<<NB1, 256>>>();
            k_mma_gemm<<<gg, 256, GEMM_SMEM>>>(in_ptr, qw, qb, Q, NN);
            k_hist<<<(EE + 255) / 256, 256>>>(dst);
            k_mma_gemm<<<gg, 256, GEMM_SMEM>>>(in_ptr, kw, kb, K, NN);
            k_scan1<<<NB1, 256>>>();
            k_mma_gemm<<<gg, 256, GEMM_SMEM>>>(in_ptr, vw, vb, V, NN);
            k_scan2<<<1, 256>>>(NB1);
            k_mma_gemm<<<gg, 256, GEMM_SMEM>>>(in_ptr, sw, sb, S, NN);
            k_scan3<<<NB1, 256>>>();
            k_fill<<<(EE + 255) / 256, 256>>>(dst);
        } else {
            k_mma_gemm<<<gg, 256, GEMM_SMEM>>>(in_ptr, qw, qb, Q, NN);
            k_mma_gemm<<<gg, 256, GEMM_SMEM>>>(in_ptr, kw, kb, K, NN);
            k_mma_gemm<<<gg, 256, GEMM_SMEM>>>(in_ptr, vw, vb, V, NN);
            k_mma_gemm<<<gg, 256, GEMM_SMEM>>>(in_ptr, sw, sb, S, NN);
        }

        k_edge<<<(NN * 32 + 255) / 256, 256>>>(ea, ew, src);

        k_zero_bn<<<1, 128>>>();
        k_bn_reduce<<<512, 128>>>();
        k_bn_apply<<<(NN * HC + 255) / 256, 256>>>(bg, bb, (L == 0) ? x1 : x2);

        in_ptr = x1;
    }
}

// round 6
// speedup vs baseline: 1.2457x; 1.0299x over previous
#include <cuda_runtime.h>
#include <cstdint>
#include <math.h>

#define NN 50000
#define EE 400000
#define HC 128
#define EDIM 16
#define BN_EPS 1e-5f

// ---------------- scratch (device globals; no allocation allowed) ----------------
__device__ float g_Q[(size_t)NN * HC];
__device__ float g_K[(size_t)NN * HC];
__device__ float g_V[(size_t)NN * HC];
__device__ float g_S[(size_t)NN * HC];        // skip; overwritten with y = attn + skip
__device__ float g_Asp[(size_t)NN * 256];     // input split: hi/lo interleaved
__device__ float g_Wsp[4][128 * 256];         // 4 weight matrices split, hi/lo interleaved

__device__ int g_deg[NN];
__device__ int g_cur[NN];
__device__ int g_off[NN + 1];
__device__ int g_eids[EE];
__device__ int g_bsum[256];
__device__ int g_boff[256];
__device__ float g_bnsum[HC];
__device__ float g_bnsq[HC];

// ---------------- tf32 split helpers ----------------
__device__ __forceinline__ void tf32_split(float a, float& h, float& l) {
    unsigned hb, lb;
    asm("cvt.rna.tf32.f32 %0, %1;" : "=r"(hb) : "f"(a));
    float hf = __uint_as_float(hb);
    float r = a - hf;
    asm("cvt.rna.tf32.f32 %0, %1;" : "=r"(lb) : "f"(r));
    h = hf;
    l = __uint_as_float(lb);
}

// pre-split A: each thread converts one float2 -> interleaved float4
__global__ void k_splitA(const float* __restrict__ A, float* __restrict__ Asp, int n2) {
    int i = blockIdx.x * blockDim.x + threadIdx.x;
    if (i >= n2) return;
    float2 v = ((const float2*)A)[i];
    float hx, lx, hy, ly;
    tf32_split(v.x, hx, lx);
    tf32_split(v.y, hy, ly);
    ((float4*)Asp)[i] = make_float4(hx, lx, hy, ly);
}

// pre-split the 4 weight matrices of one layer
__global__ void k_splitW(const float* __restrict__ w0, const float* __restrict__ w1,
                         const float* __restrict__ w2, const float* __restrict__ w3) {
    int i = blockIdx.x * blockDim.x + threadIdx.x;   // 0 .. 4*8192-1
    if (i >= 4 * 8192) return;
    int which = i >> 13;
    int j = i & 8191;
    const float* w = which == 0 ? w0 : which == 1 ? w1 : which == 2 ? w2 : w3;
    float2 v = ((const float2*)w)[j];
    float hx, lx, hy, ly;
    tf32_split(v.x, hx, lx);
    tf32_split(v.y, hy, ly);
    ((float4*)&g_Wsp[which][0])[j] = make_float4(hx, lx, hy, ly);
}

// ---------------- CSR build ----------------
__global__ void k_zero_csr() {
    int i = blockIdx.x * blockDim.x + threadIdx.x;
    if (i < NN) { g_deg[i] = 0; g_cur[i] = 0; }
}

__global__ void k_hist(const int* __restrict__ dst) {
    int e = blockIdx.x * blockDim.x + threadIdx.x;
    if (e < EE) atomicAdd(&g_deg[dst[e]], 1);
}

__global__ void k_scan1() {
    __shared__ int sh[256];
    int tid = threadIdx.x;
    int i = blockIdx.x * 256 + tid;
    int v = (i < NN) ? g_deg[i] : 0;
    sh[tid] = v;
    __syncthreads();
    for (int o = 1; o < 256; o <<= 1) {
        int t = (tid >= o) ? sh[tid - o] : 0;
        __syncthreads();
        sh[tid] += t;
        __syncthreads();
    }
    if (i < NN) g_off[i] = sh[tid] - v;
    if (tid == 255) g_bsum[blockIdx.x] = sh[255];
}

__global__ void k_scan2(int nb) {
    __shared__ int sh[256];
    int tid = threadIdx.x;
    int v = (tid < nb) ? g_bsum[tid] : 0;
    sh[tid] = v;
    __syncthreads();
    for (int o = 1; o < 256; o <<= 1) {
        int t = (tid >= o) ? sh[tid - o] : 0;
        __syncthreads();
        sh[tid] += t;
        __syncthreads();
    }
    g_boff[tid] = sh[tid] - v;
}

__global__ void k_scan3() {
    int i = blockIdx.x * 256 + threadIdx.x;
    if (i < NN) g_off[i] += g_boff[blockIdx.x];
    if (i == 0) g_off[NN] = EE;
}

__global__ void k_fill(const int* __restrict__ dst) {
    int e = blockIdx.x * blockDim.x + threadIdx.x;
    if (e < EE) {
        int d = dst[e];
        int pos = g_off[d] + atomicAdd(&g_cur[d], 1);
        g_eids[pos] = e;
    }
}

// ---------------- fused 3xTF32 tensor-core GEMM (Q,K,V,S in one launch) ----------------
// C[M,128] = A[M,128] @ W[128,128] + bias, blockIdx.y selects {Q,K,V,S}
// BM=128, BN=128, BK=32 x 4 chunks. 8 warps, warp tile 64x32.
// smem: hi/lo interleaved pairs; copies are raw cp.async (operands pre-split).
#define SA2 72    // A smem row stride in floats (32*2 + 8 pad)
#define SB2 264   // B smem row stride in floats (128*2 + 8 pad)
#define G4_SMEM ((128 * SA2 + 32 * SB2) * 4)   // 70656 bytes

__device__ __forceinline__ void cpa16(unsigned int dst, const void* src, int bytes) {
    asm volatile("cp.async.ca.shared.global [%0], [%1], 16, %2;\n"
                 :: "r"(dst), "l"(src), "r"(bytes));
}

__device__ __forceinline__ void mma8(float* d, unsigned a0, unsigned a1, unsigned a2,
                                     unsigned a3, unsigned b0, unsigned b1) {
    asm volatile(
        "mma.sync.aligned.m16n8k8.row.col.f32.tf32.tf32.f32 "
        "{%0,%1,%2,%3}, {%4,%5,%6,%7}, {%8,%9}, {%0,%1,%2,%3};\n"
        : "+f"(d[0]), "+f"(d[1]), "+f"(d[2]), "+f"(d[3])
        : "r"(a0), "r"(a1), "r"(a2), "r"(a3), "r"(b0), "r"(b1));
}

__global__ void __launch_bounds__(256, 2) k_gemm4(
    const float* __restrict__ Asp,
    const float* __restrict__ b0p, const float* __restrict__ b1p,
    const float* __restrict__ b2p, const float* __restrict__ b3p,
    float* __restrict__ o0p, float* __restrict__ o1p,
    float* __restrict__ o2p, float* __restrict__ o3p, int M)
{
    extern __shared__ float sm[];
    float* As = sm;               // [128][SA2]
    float* Bs = sm + 128 * SA2;   // [32][SB2]
    unsigned int As_u = (unsigned int)__cvta_generic_to_shared(As);
    unsigned int Bs_u = (unsigned int)__cvta_generic_to_shared(Bs);

    int tid = threadIdx.x;
    int wid = tid >> 5, lane = tid & 31;
    int g = lane >> 2, tig = lane & 3;
    int m0 = (wid & 1) * 64;
    int n0 = (wid >> 1) * 32;
    int brow = blockIdx.x * 128;
    int which = blockIdx.y;

    const float* W = &g_Wsp[which][0];
    const float* bias = which == 0 ? b0p : which == 1 ? b1p : which == 2 ? b2p : b3p;
    float* C = which == 0 ? o0p : which == 1 ? o1p : which == 2 ? o2p : o3p;

    float acc[4][4][4];
#pragma unroll
    for (int i = 0; i < 4; i++)
#pragma unroll
        for (int j = 0; j < 4; j++)
#pragma unroll
            for (int r = 0; r < 4; r++) acc[i][j][r] = 0.f;

    for (int k0 = 0; k0 < 128; k0 += 32) {
        // A chunk: 128 rows x 16 float4 (64 floats = 32 k pre-split pairs)
#pragma unroll
        for (int j = 0; j < 8; j++) {
            int idx = tid + j * 256;        // 0..2047
            int row = idx >> 4;
            int c4 = idx & 15;
            int grow = brow + row;
            int nb = (grow < M) ? 16 : 0;
            cpa16(As_u + (row * SA2 + c4 * 4) * 4,
                  &Asp[(size_t)grow * 256 + k0 * 2 + c4 * 4], nb);
        }
        // B chunk: 32 rows x 64 float4 (256 floats)
#pragma unroll
        for (int j = 0; j < 8; j++) {
            int idx = tid + j * 256;        // 0..2047
            int row = idx >> 6;
            int c4 = idx & 63;
            cpa16(Bs_u + (row * SB2 + c4 * 4) * 4,
                  &W[(size_t)(k0 + row) * 256 + c4 * 4], 16);
        }
        asm volatile("cp.async.commit_group;\n");
        asm volatile("cp.async.wait_group 0;\n");
        __syncthreads();

#pragma unroll
        for (int ks = 0; ks < 4; ks++) {
            int kk = ks * 8;
            unsigned ah[4][4], al[4][4];
#pragma unroll
            for (int mf = 0; mf < 4; mf++) {
                const float* ab = &As[(m0 + mf * 16 + g) * SA2 + 2 * (kk + tig)];
                float2 v0 = *(const float2*)ab;              // (g,   k)
                float2 v2 = *(const float2*)(ab + 8);        // (g,   k+4)
                float2 v1 = *(const float2*)(ab + 8 * SA2);  // (g+8, k)
                float2 v3 = *(const float2*)(ab + 8 * SA2 + 8);
                ah[mf][0] = __float_as_uint(v0.x); al[mf][0] = __float_as_uint(v0.y);
                ah[mf][1] = __float_as_uint(v1.x); al[mf][1] = __float_as_uint(v1.y);
                ah[mf][2] = __float_as_uint(v2.x); al[mf][2] = __float_as_uint(v2.y);
                ah[mf][3] = __float_as_uint(v3.x); al[mf][3] = __float_as_uint(v3.y);
            }
#pragma unroll
            for (int nf = 0; nf < 4; nf++) {
                const float* bp = &Bs[(kk + tig) * SB2 + 2 * (n0 + nf * 8 + g)];
                float2 w0 = *(const float2*)bp;              // (k,   n)
                float2 w1 = *(const float2*)(bp + 4 * SB2);  // (k+4, n)
                unsigned bh0 = __float_as_uint(w0.x), bl0 = __float_as_uint(w0.y);
                unsigned bh1 = __float_as_uint(w1.x), bl1 = __float_as_uint(w1.y);
#pragma unroll
                for (int mf = 0; mf < 4; mf++) {
                    float* d = acc[mf][nf];
                    mma8(d, ah[mf][0], ah[mf][1], ah[mf][2], ah[mf][3], bh0, bh1);
                    mma8(d, ah[mf][0], ah[mf][1], ah[mf][2], ah[mf][3], bl0, bl1);
                    mma8(d, al[mf][0], al[mf][1], al[mf][2], al[mf][3], bh0, bh1);
                }
            }
        }
        __syncthreads();
    }

    // epilogue: add bias, store
#pragma unroll
    for (int nf = 0; nf < 4; nf++) {
        int col = n0 + nf * 8 + tig * 2;
        float b0v = bias[col], b1v = bias[col + 1];
#pragma unroll
        for (int mf = 0; mf < 4; mf++) {
            int r0 = brow + m0 + mf * 16 + g;
            float* d = acc[mf][nf];
            if (r0 < M)
                *(float2*)&C[(size_t)r0 * 128 + col] = make_float2(d[0] + b0v, d[1] + b1v);
            if (r0 + 8 < M)
                *(float2*)&C[(size_t)(r0 + 8) * 128 + col] = make_float2(d[2] + b0v, d[3] + b1v);
        }
    }
}

// ---------------- edge attention: one warp per dst node, online softmax ----------------
__global__ void __launch_bounds__(256) k_edge(
    const float* __restrict__ EA,   // [E,16]
    const float* __restrict__ EW,   // [16,128]
    const int* __restrict__ src)
{
    __shared__ __align__(16) float4 ews[16 * 32];
    for (int i = threadIdx.x; i < 16 * 32; i += 256)
        ews[i] = ((const float4*)EW)[i];
    __syncthreads();

    int warp = (blockIdx.x * 256 + threadIdx.x) >> 5;
    int lane = threadIdx.x & 31;
    if (warp >= NN) return;
    int node = warp;
    int beg = g_off[node], end = g_off[node + 1];

    float4 qv = *(const float4*)&g_Q[(size_t)node * HC + lane * 4];

    float m = -1e30f;
    float s = 0.f;
    float ax = 0.f, ay = 0.f, az = 0.f, aw = 0.f;

    for (int p = beg; p < end; p++) {
        int e = g_eids[p];
        int sn = src[e];
        float eav = (lane < EDIM) ? EA[(size_t)e * EDIM + lane] : 0.f;

        float ex = 0.f, ey = 0.f, ez = 0.f, ew_ = 0.f;
#pragma unroll
        for (int d = 0; d < EDIM; d++) {
            float w = __shfl_sync(0xffffffffu, eav, d);
            float4 wc = ews[d * 32 + lane];
            ex += w * wc.x; ey += w * wc.y; ez += w * wc.z; ew_ += w * wc.w;
        }

        float4 kv = *(const float4*)&g_K[(size_t)sn * HC + lane * 4];
        float4 vv = *(const float4*)&g_V[(size_t)sn * HC + lane * 4];

        float part = qv.x * (kv.x + ex) + qv.y * (kv.y + ey)
                   + qv.z * (kv.z + ez) + qv.w * (kv.w + ew_);
        part += __shfl_xor_sync(0xffffffffu, part, 1);
        part += __shfl_xor_sync(0xffffffffu, part, 2);
        part += __shfl_xor_sync(0xffffffffu, part, 4);
        float a = part * 0.17677669529663687f;   // 1/sqrt(32)

        float nm = fmaxf(m, a);
        float sc = __expf(m - nm);
        float pe = __expf(a - nm);
        s = s * sc + pe;
        ax = ax * sc + pe * (vv.x + ex);
        ay = ay * sc + pe * (vv.y + ey);
        az = az * sc + pe * (vv.z + ez);
        aw = aw * sc + pe * (vv.w + ew_);
        m = nm;
    }

    float inv = (end > beg) ? (1.f / s) : 0.f;
    size_t o = (size_t)node * HC + lane * 4;
    float4 sv = *(const float4*)&g_S[o];
    float4 y = make_float4(ax * inv + sv.x, ay * inv + sv.y,
                           az * inv + sv.z, aw * inv + sv.w);
    *(float4*)&g_S[o] = y;   // y = attn_out + skip (in place)
}

// ---------------- batchnorm + relu ----------------
__global__ void k_zero_bn() {
    int t = threadIdx.x;
    if (t < HC) { g_bnsum[t] = 0.f; g_bnsq[t] = 0.f; }
}

__global__ void k_bn_reduce() {
    int c = threadIdx.x;
    float sum = 0.f, sq = 0.f;
    for (int n = blockIdx.x; n < NN; n += gridDim.x) {
        float v = g_S[(size_t)n * HC + c];
        sum += v; sq += v * v;
    }
    atomicAdd(&g_bnsum[c], sum);
    atomicAdd(&g_bnsq[c], sq);
}

__global__ void k_bn_apply(const float* __restrict__ gamma,
                           const float* __restrict__ beta,
                           float* __restrict__ out)
{
    int i = blockIdx.x * blockDim.x + threadIdx.x;
    if (i >= NN * HC) return;
    int c = i & 127;
    float mean = g_bnsum[c] * (1.f / NN);
    float var = fmaf(-mean, mean, g_bnsq[c] * (1.f / NN));
    float v = (g_S[i] - mean) * rsqrtf(var + BN_EPS) * gamma[c] + beta[c];
    out[i] = fmaxf(v, 0.f);
}

// ---------------- driver ----------------
extern "C" void kernel_launch(void* const* d_in, const int* in_sizes, int n_in,
                              void* d_out, int out_size)
{
    const float* x  = (const float*)d_in[0];
    const int*   ei = (const int*)d_in[1];
    const float* ea = (const float*)d_in[2];
    const int* src = ei;
    const int* dst = ei + EE;

    float* out = (float*)d_out;
    float* x1 = out;
    float* x2 = out + (size_t)NN * HC;

    float *Q, *K, *V, *S, *Asp;
    cudaGetSymbolAddress((void**)&Q, g_Q);
    cudaGetSymbolAddress((void**)&K, g_K);
    cudaGetSymbolAddress((void**)&V, g_V);
    cudaGetSymbolAddress((void**)&S, g_S);
    cudaGetSymbolAddress((void**)&Asp, g_Asp);

    cudaFuncSetAttribute(k_gemm4, cudaFuncAttributeMaxDynamicSharedMemorySize, G4_SMEM);

    const int NB1 = (NN + 255) / 256;
    const dim3 gg4((NN + 127) / 128, 4);
    const int nsplit2 = NN * 64;   // float2 count per A

    const float* in_ptr = x;
    for (int L = 0; L < 2; L++) {
        int b = 3 + L * 11;
        const float* qw = (const float*)d_in[b + 0];
        const float* qb = (const float*)d_in[b + 1];
        const float* kw = (const float*)d_in[b + 2];
        const float* kb = (const float*)d_in[b + 3];
        const float* vw = (const float*)d_in[b + 4];
        const float* vb = (const float*)d_in[b + 5];
        const float* ew = (const float*)d_in[b + 6];
        const float* sw = (const float*)d_in[b + 7];
        const float* sb = (const float*)d_in[b + 8];
        const float* bg = (const float*)d_in[b + 9];
        const float* bb = (const float*)d_in[b + 10];

        if (L == 0) {
            // order chosen so ncu -s 5 -c 1 profiles k_gemm4 (launch index 5)
            k_splitA<<<(nsplit2 + 255) / 256, 256>>>(in_ptr, Asp, nsplit2);        // 0
            k_splitW<<<128, 256>>>(qw, kw, vw, sw);                                // 1
            k_zero_csr<<<NB1, 256>>>();                                            // 2
            k_hist<<<(EE + 255) / 256, 256>>>(dst);                                // 3
            k_scan1<<<NB1, 256>>>();                                               // 4
            k_gemm4<<<gg4, 256, G4_SMEM>>>(Asp, qb, kb, vb, sb, Q, K, V, S, NN);   // 5
            k_scan2<<<1, 256>>>(NB1);
            k_scan3<<<NB1, 256>>>();
            k_fill<<<(EE + 255) / 256, 256>>>(dst);
        } else {
            k_splitA<<<(nsplit2 + 255) / 256, 256>>>(in_ptr, Asp, nsplit2);
            k_splitW<<<128, 256>>>(qw, kw, vw, sw);
            k_gemm4<<<gg4, 256, G4_SMEM>>>(Asp, qb, kb, vb, sb, Q, K, V, S, NN);
        }

        k_edge<<<(NN * 32 + 255) / 256, 256>>>(ea, ew, src);

        k_zero_bn<<<1, 128>>>();
        k_bn_reduce<<<512, 128>>>();
        k_bn_apply<<<(NN * HC + 255) / 256, 256>>>(bg, bb, (L == 0) ? x1 : x2);

        in_ptr = x1;
    }
}